// round 10
// baseline (speedup 1.0000x reference)
#include <cuda_runtime.h>
#include <cstdint>

// Problem constants
#define NN   65536   // nodes
#define BB   128     // batch
#define TT   16      // timesteps
#define IBK  256     // input bits per step (w_in = arange(IBK))
#define OO   10      // readout outputs

// ---------------- static device scratch ----------------
__device__ uint4    g_state[2][NN + 1];      // batch-packed state; entry NN = permanent zero
__device__ unsigned g_lut[NN * 8];           // 256-bit packed LUT row per node
__device__ int      g_eadj[NN * 8];          // adjacency with mask pre-merged (masked -> NN)
__device__ uint4    g_xp[TT * IBK];          // per-step batch-packed input bits
__device__ float    g_partial[256 * 128 * OO];

// ---------------- preprocessing: pack lut bits (64MB -> 2MB) ----------------
__global__ void pack_lut_kernel(const int* __restrict__ lut) {
    int gw   = (blockIdx.x * blockDim.x + threadIdx.x) >> 5;
    int lane = threadIdx.x & 31;
    const int* row = lut + (size_t)gw * 256;
    unsigned myword = 0;
    #pragma unroll
    for (int w = 0; w < 8; w++) {
        int v = row[w * 32 + lane];
        unsigned bal = __ballot_sync(0xFFFFFFFFu, v & 1);
        if (lane == w) myword = bal;
    }
    if (lane < 8) g_lut[gw * 8 + lane] = myword;
}

// ---------------- preprocessing: merge mask into adjacency ----------------
__global__ void merge_adj_kernel(const int* __restrict__ adj, const int* __restrict__ msk) {
    int i = blockIdx.x * blockDim.x + threadIdx.x;
    int a = adj[i];
    int m = msk[i];
    g_eadj[i] = (m != 0) ? a : NN;
}

// ---------------- preprocessing: pack x into batch-bit words ----------------
__global__ void pack_x_kernel(const int* __restrict__ x, const int* __restrict__ w_in) {
    int gw   = (blockIdx.x * blockDim.x + threadIdx.x) >> 5;
    int lane = threadIdx.x & 31;
    int t = gw >> 8;
    int i = gw & 255;
    unsigned bw[4];
    #pragma unroll
    for (int w = 0; w < 4; w++) {
        int b = w * 32 + lane;
        int v = x[(b * TT + t) * IBK + i];
        bw[w] = __ballot_sync(0xFFFFFFFFu, v & 1);
    }
    if (lane == 0) {
        int node = w_in[i];
        if ((unsigned)node < IBK) {
            uint4 v; v.x = bw[0]; v.y = bw[1]; v.z = bw[2]; v.w = bw[3];
            g_xp[t * IBK + node] = v;
        }
    }
}

// ---------------- init: broadcast init_state across batch, fuse x[t=0] XOR ----------------
__global__ void init_state_kernel(const int* __restrict__ init_state) {
    int n = blockIdx.x * blockDim.x + threadIdx.x;
    unsigned v = (unsigned)(-(init_state[n] & 1));
    uint4 s; s.x = v; s.y = v; s.z = v; s.w = v;
    if (n < IBK) {
        uint4 xv = g_xp[n];     // t = 0
        s.x ^= xv.x; s.y ^= xv.y; s.z ^= xv.z; s.w ^= xv.w;
    }
    g_state[0][n] = s;
    if (n == 0) {
        uint4 z; z.x = z.y = z.z = z.w = 0u;
        g_state[0][NN] = z;
        g_state[1][NN] = z;
    }
}

// ---------------- one reservoir step ----------------
// 128 threads/CTA, 512 CTAs. Conflict-free LDS: LUT stored word-major
// slut[w*128 + tid] -> bank = tid mod 32 regardless of the random word index.
__global__ void __launch_bounds__(128) step_kernel(int t) {
    __shared__ unsigned slut[8 * 128];   // [word][thread] -- bank = tid%32 always
    const int tid = threadIdx.x;
    const int n   = blockIdx.x * 128 + tid;
    const uint4* __restrict__ sin  = g_state[t & 1];
    uint4* __restrict__       sout = g_state[(t + 1) & 1];

    // independent loads first: LUT row + adjacency
    const uint4* lr = (const uint4*)&g_lut[n * 8];
    uint4 lA = __ldg(lr);
    uint4 lB = __ldg(lr + 1);

    const int4* ea4 = (const int4*)g_eadj;
    int4 a0 = __ldg(&ea4[n * 2]);
    int4 a1 = __ldg(&ea4[n * 2 + 1]);

    // issue the 8 random gathers ASAP
    uint4 v0 = __ldg(&sin[a0.x]);
    uint4 v1 = __ldg(&sin[a0.y]);
    uint4 v2 = __ldg(&sin[a0.z]);
    uint4 v3 = __ldg(&sin[a0.w]);
    uint4 v4 = __ldg(&sin[a1.x]);
    uint4 v5 = __ldg(&sin[a1.y]);
    uint4 v6 = __ldg(&sin[a1.z]);
    uint4 v7 = __ldg(&sin[a1.w]);

    // stage LUT row word-major (conflict-free stores: fixed w, lanes distinct banks)
    slut[0 * 128 + tid] = lA.x;
    slut[1 * 128 + tid] = lA.y;
    slut[2 * 128 + tid] = lA.z;
    slut[3 * 128 + tid] = lA.w;
    slut[4 * 128 + tid] = lB.x;
    slut[5 * 128 + tid] = lB.y;
    slut[6 * 128 + tid] = lB.z;
    slut[7 * 128 + tid] = lB.w;
    const unsigned* myl = &slut[tid];   // element w at myl[w*128]

    unsigned nbw[8][4];
    nbw[0][0]=v0.x; nbw[0][1]=v0.y; nbw[0][2]=v0.z; nbw[0][3]=v0.w;
    nbw[1][0]=v1.x; nbw[1][1]=v1.y; nbw[1][2]=v1.z; nbw[1][3]=v1.w;
    nbw[2][0]=v2.x; nbw[2][1]=v2.y; nbw[2][2]=v2.z; nbw[2][3]=v2.w;
    nbw[3][0]=v3.x; nbw[3][1]=v3.y; nbw[3][2]=v3.z; nbw[3][3]=v3.w;
    nbw[4][0]=v4.x; nbw[4][1]=v4.y; nbw[4][2]=v4.z; nbw[4][3]=v4.w;
    nbw[5][0]=v5.x; nbw[5][1]=v5.y; nbw[5][2]=v5.z; nbw[5][3]=v5.w;
    nbw[6][0]=v6.x; nbw[6][1]=v6.y; nbw[6][2]=v6.z; nbw[6][3]=v6.w;
    nbw[7][0]=v7.x; nbw[7][1]=v7.y; nbw[7][2]=v7.z; nbw[7][3]=v7.w;

    unsigned outw[4];
    #pragma unroll
    for (int l = 0; l < 4; l++) {     // 32 batches per lane word
        unsigned r0 = nbw[0][l], r1 = nbw[1][l], r2 = nbw[2][l], r3 = nbw[3][l];
        unsigned r4 = nbw[4][l], r5 = nbw[5][l], r6 = nbw[6][l], r7 = nbw[7][l];
        unsigned acc = 0;
        #pragma unroll
        for (int g = 0; g < 4; g++) { // byte group = 8 batches
            const unsigned s01 = (unsigned)(g | ((g + 4) << 4));
            unsigned t76 = __byte_perm(r7, r6, s01);
            unsigned t54 = __byte_perm(r5, r4, s01);
            unsigned t32 = __byte_perm(r3, r2, s01);
            unsigned t10 = __byte_perm(r1, r0, s01);
            unsigned xl  = __byte_perm(t76, t54, 0x5410);
            unsigned xh  = __byte_perm(t32, t10, 0x5410);

            // fused 8x8 bit transpose of 64-bit (xh:xl)
            unsigned lo = __funnelshift_r(xl, xh, 7);
            unsigned hi = xh >> 7;
            unsigned tl = (xl ^ lo) & 0x00AA00AAu;
            unsigned th = (xh ^ hi) & 0x00AA00AAu;
            xl ^= tl ^ (tl << 7);
            xh ^= th ^ (th << 7);
            lo = __funnelshift_r(xl, xh, 14);
            hi = xh >> 14;
            tl = (xl ^ lo) & 0x0000CCCCu;
            th = (xh ^ hi) & 0x0000CCCCu;
            xl ^= tl ^ (tl << 14);
            xh ^= th ^ (th << 14);
            lo = __funnelshift_r(xl, xh, 28);
            tl = (xl ^ lo) & 0xF0F0F0F0u;
            xl ^= tl;
            xh ^= tl >> 4;

            // byte i of (xh:xl) = 8-bit LUT index of batch 8g+i
            #pragma unroll
            for (int b = 0; b < 8; b++) {
                unsigned src = (b < 4) ? xl : xh;
                unsigned idx = __byte_perm(src, 0u, 0x4440u + (unsigned)(b & 3));
                unsigned w   = myl[(idx >> 5) * 128];
                unsigned pos = (unsigned)(g * 8 + b);
                acc |= __funnelshift_r(w, w, idx - pos) & (1u << pos);
            }
        }
        outw[l] = acc;
    }

    uint4 o; o.x = outw[0]; o.y = outw[1]; o.z = outw[2]; o.w = outw[3];
    if (t < TT - 1 && n < IBK) {
        uint4 xv = g_xp[(t + 1) * IBK + n];
        o.x ^= xv.x; o.y ^= xv.y; o.z ^= xv.z; o.w ^= xv.w;
    }
    sout[n] = o;
}

// ---------------- readout phase 1: deterministic partials ----------------
__global__ void readout_kernel(const float* __restrict__ wro) {
    int c   = blockIdx.x;
    int b   = threadIdx.x & 127;
    int sub = threadIdx.x >> 7;
    int wsel = b >> 5;
    int bit  = b & 31;
    float acc[OO];
    #pragma unroll
    for (int o = 0; o < OO; o++) acc[o] = 0.0f;

    const unsigned* st = (const unsigned*)g_state[0];  // final state after 16 steps
    int n0 = c * 512 + sub * 256;
    for (int n = n0; n < n0 + 256; n++) {
        unsigned wrd = __ldg(&st[n * 4 + wsel]);
        float f = (float)((wrd >> bit) & 1u);
        #pragma unroll
        for (int o = 0; o < OO; o++)
            acc[o] += f * __ldg(&wro[o * NN + n]);
    }
    float* p = &g_partial[(size_t)((c * 2 + sub) * 128 + b) * OO];
    #pragma unroll
    for (int o = 0; o < OO; o++) p[o] = acc[o];
}

// ---------------- readout phase 2 ----------------
__global__ void finalize_kernel(const float* __restrict__ b_readout, float* __restrict__ out) {
    int i = blockIdx.x * blockDim.x + threadIdx.x;
    if (i >= BB * OO) return;
    int b = i / OO;
    int o = i % OO;
    float sum = 0.0f;
    for (int c = 0; c < 256; c++)
        sum += g_partial[(size_t)(c * 128 + b) * OO + o];
    sum += b_readout[o];
    out[i] = 1.0f / (1.0f + expf(-sum));
}

// ---------------- launch ----------------
extern "C" void kernel_launch(void* const* d_in, const int* in_sizes, int n_in,
                              void* d_out, int out_size) {
    const int*   x          = (const int*)d_in[0];
    const int*   adj_list   = (const int*)d_in[1];
    const int*   adj_mask   = (const int*)d_in[2];
    const int*   lut        = (const int*)d_in[3];
    const int*   init_state = (const int*)d_in[4];
    const int*   w_in       = (const int*)d_in[5];
    const float* w_readout  = (const float*)d_in[6];
    const float* b_readout  = (const float*)d_in[7];
    float*       out        = (float*)d_out;

    pack_lut_kernel<<<(NN * 32) / 256, 256>>>(lut);
    merge_adj_kernel<<<(NN * 8) / 256, 256>>>(adj_list, adj_mask);
    pack_x_kernel<<<(TT * IBK * 32) / 256, 256>>>(x, w_in);
    init_state_kernel<<<NN / 256, 256>>>(init_state);
    for (int t = 0; t < TT; t++)
        step_kernel<<<NN / 128, 128>>>(t);
    readout_kernel<<<128, 256>>>(w_readout);
    finalize_kernel<<<(BB * OO + 255) / 256, 256>>>(b_readout, out);
}

// round 11
// speedup vs baseline: 1.0031x; 1.0031x over previous
#include <cuda_runtime.h>
#include <cstdint>

// Problem constants
#define NN   65536   // nodes
#define BB   128     // batch
#define TT   16      // timesteps
#define IBK  256     // input bits per step (w_in = arange(IBK))
#define OO   10      // readout outputs

// ---------------- static device scratch ----------------
__device__ uint4    g_state[2][NN + 1];      // batch-packed state; entry NN = permanent zero
__device__ unsigned g_lut[NN * 8];           // 256-bit packed LUT row per node
__device__ int      g_eadj[NN * 8];          // adjacency with mask pre-merged (masked -> NN)
__device__ uint4    g_xp[TT * IBK];          // per-step batch-packed input bits
__device__ float    g_partial[256 * 128 * OO];

// ---------------- preprocessing: pack lut bits (64MB -> 2MB) ----------------
__global__ void pack_lut_kernel(const int* __restrict__ lut) {
    int gw   = (blockIdx.x * blockDim.x + threadIdx.x) >> 5;
    int lane = threadIdx.x & 31;
    const int* row = lut + (size_t)gw * 256;
    unsigned myword = 0;
    #pragma unroll
    for (int w = 0; w < 8; w++) {
        int v = row[w * 32 + lane];
        unsigned bal = __ballot_sync(0xFFFFFFFFu, v & 1);
        if (lane == w) myword = bal;
    }
    if (lane < 8) g_lut[gw * 8 + lane] = myword;
}

// ---------------- preprocessing: merge mask into adjacency ----------------
__global__ void merge_adj_kernel(const int* __restrict__ adj, const int* __restrict__ msk) {
    int i = blockIdx.x * blockDim.x + threadIdx.x;
    int a = adj[i];
    int m = msk[i];
    g_eadj[i] = (m != 0) ? a : NN;
}

// ---------------- preprocessing: pack x into batch-bit words ----------------
__global__ void pack_x_kernel(const int* __restrict__ x, const int* __restrict__ w_in) {
    int gw   = (blockIdx.x * blockDim.x + threadIdx.x) >> 5;
    int lane = threadIdx.x & 31;
    int t = gw >> 8;
    int i = gw & 255;
    unsigned bw[4];
    #pragma unroll
    for (int w = 0; w < 4; w++) {
        int b = w * 32 + lane;
        int v = x[(b * TT + t) * IBK + i];
        bw[w] = __ballot_sync(0xFFFFFFFFu, v & 1);
    }
    if (lane == 0) {
        int node = w_in[i];
        if ((unsigned)node < IBK) {
            uint4 v; v.x = bw[0]; v.y = bw[1]; v.z = bw[2]; v.w = bw[3];
            g_xp[t * IBK + node] = v;
        }
    }
}

// ---------------- init: broadcast init_state across batch, fuse x[t=0] XOR ----------------
__global__ void init_state_kernel(const int* __restrict__ init_state) {
    int n = blockIdx.x * blockDim.x + threadIdx.x;
    unsigned v = (unsigned)(-(init_state[n] & 1));
    uint4 s; s.x = v; s.y = v; s.z = v; s.w = v;
    if (n < IBK) {
        uint4 xv = g_xp[n];     // t = 0
        s.x ^= xv.x; s.y ^= xv.y; s.z ^= xv.z; s.w ^= xv.w;
    }
    g_state[0][n] = s;
    if (n == 0) {
        uint4 z; z.x = z.y = z.z = z.w = 0u;
        g_state[0][NN] = z;
        g_state[1][NN] = z;
    }
}

// ---------------- one reservoir step ----------------
// 128 threads/CTA, 512 CTAs. Conflict-free LDS: LUT stored word-major
// slut[w*128 + tid] -> bank = tid mod 32 regardless of the random word index.
__global__ void __launch_bounds__(128) step_kernel(int t) {
    __shared__ unsigned slut[8 * 128];   // [word][thread] -- bank = tid%32 always
    const int tid = threadIdx.x;
    const int n   = blockIdx.x * 128 + tid;
    const uint4* __restrict__ sin  = g_state[t & 1];
    uint4* __restrict__       sout = g_state[(t + 1) & 1];

    // independent loads first: LUT row + adjacency
    const uint4* lr = (const uint4*)&g_lut[n * 8];
    uint4 lA = __ldg(lr);
    uint4 lB = __ldg(lr + 1);

    const int4* ea4 = (const int4*)g_eadj;
    int4 a0 = __ldg(&ea4[n * 2]);
    int4 a1 = __ldg(&ea4[n * 2 + 1]);

    // issue the 8 random gathers ASAP
    uint4 v0 = __ldg(&sin[a0.x]);
    uint4 v1 = __ldg(&sin[a0.y]);
    uint4 v2 = __ldg(&sin[a0.z]);
    uint4 v3 = __ldg(&sin[a0.w]);
    uint4 v4 = __ldg(&sin[a1.x]);
    uint4 v5 = __ldg(&sin[a1.y]);
    uint4 v6 = __ldg(&sin[a1.z]);
    uint4 v7 = __ldg(&sin[a1.w]);

    // stage LUT row word-major (conflict-free stores: fixed w, lanes distinct banks)
    slut[0 * 128 + tid] = lA.x;
    slut[1 * 128 + tid] = lA.y;
    slut[2 * 128 + tid] = lA.z;
    slut[3 * 128 + tid] = lA.w;
    slut[4 * 128 + tid] = lB.x;
    slut[5 * 128 + tid] = lB.y;
    slut[6 * 128 + tid] = lB.z;
    slut[7 * 128 + tid] = lB.w;
    const unsigned* myl = &slut[tid];   // element w at myl[w*128]

    unsigned nbw[8][4];
    nbw[0][0]=v0.x; nbw[0][1]=v0.y; nbw[0][2]=v0.z; nbw[0][3]=v0.w;
    nbw[1][0]=v1.x; nbw[1][1]=v1.y; nbw[1][2]=v1.z; nbw[1][3]=v1.w;
    nbw[2][0]=v2.x; nbw[2][1]=v2.y; nbw[2][2]=v2.z; nbw[2][3]=v2.w;
    nbw[3][0]=v3.x; nbw[3][1]=v3.y; nbw[3][2]=v3.z; nbw[3][3]=v3.w;
    nbw[4][0]=v4.x; nbw[4][1]=v4.y; nbw[4][2]=v4.z; nbw[4][3]=v4.w;
    nbw[5][0]=v5.x; nbw[5][1]=v5.y; nbw[5][2]=v5.z; nbw[5][3]=v5.w;
    nbw[6][0]=v6.x; nbw[6][1]=v6.y; nbw[6][2]=v6.z; nbw[6][3]=v6.w;
    nbw[7][0]=v7.x; nbw[7][1]=v7.y; nbw[7][2]=v7.z; nbw[7][3]=v7.w;

    unsigned outw[4];
    #pragma unroll
    for (int l = 0; l < 4; l++) {     // 32 batches per lane word
        unsigned r0 = nbw[0][l], r1 = nbw[1][l], r2 = nbw[2][l], r3 = nbw[3][l];
        unsigned r4 = nbw[4][l], r5 = nbw[5][l], r6 = nbw[6][l], r7 = nbw[7][l];
        unsigned acc = 0;
        #pragma unroll
        for (int g = 0; g < 4; g++) { // byte group = 8 batches
            const unsigned s01 = (unsigned)(g | ((g + 4) << 4));
            unsigned t76 = __byte_perm(r7, r6, s01);
            unsigned t54 = __byte_perm(r5, r4, s01);
            unsigned t32 = __byte_perm(r3, r2, s01);
            unsigned t10 = __byte_perm(r1, r0, s01);
            unsigned xl  = __byte_perm(t76, t54, 0x5410);
            unsigned xh  = __byte_perm(t32, t10, 0x5410);

            // fused 8x8 bit transpose of 64-bit (xh:xl)
            unsigned lo = __funnelshift_r(xl, xh, 7);
            unsigned hi = xh >> 7;
            unsigned tl = (xl ^ lo) & 0x00AA00AAu;
            unsigned th = (xh ^ hi) & 0x00AA00AAu;
            xl ^= tl ^ (tl << 7);
            xh ^= th ^ (th << 7);
            lo = __funnelshift_r(xl, xh, 14);
            hi = xh >> 14;
            tl = (xl ^ lo) & 0x0000CCCCu;
            th = (xh ^ hi) & 0x0000CCCCu;
            xl ^= tl ^ (tl << 14);
            xh ^= th ^ (th << 14);
            lo = __funnelshift_r(xl, xh, 28);
            tl = (xl ^ lo) & 0xF0F0F0F0u;
            xl ^= tl;
            xh ^= tl >> 4;

            // byte i of (xh:xl) = 8-bit LUT index of batch 8g+i
            #pragma unroll
            for (int b = 0; b < 8; b++) {
                unsigned src = (b < 4) ? xl : xh;
                unsigned idx = __byte_perm(src, 0u, 0x4440u + (unsigned)(b & 3));
                unsigned w   = myl[(idx >> 5) * 128];
                unsigned pos = (unsigned)(g * 8 + b);
                acc |= __funnelshift_r(w, w, idx - pos) & (1u << pos);
            }
        }
        outw[l] = acc;
    }

    uint4 o; o.x = outw[0]; o.y = outw[1]; o.z = outw[2]; o.w = outw[3];
    if (t < TT - 1 && n < IBK) {
        uint4 xv = g_xp[(t + 1) * IBK + n];
        o.x ^= xv.x; o.y ^= xv.y; o.z ^= xv.z; o.w ^= xv.w;
    }
    sout[n] = o;
}

// ---------------- readout phase 1: deterministic partials ----------------
__global__ void readout_kernel(const float* __restrict__ wro) {
    int c   = blockIdx.x;
    int b   = threadIdx.x & 127;
    int sub = threadIdx.x >> 7;
    int wsel = b >> 5;
    int bit  = b & 31;
    float acc[OO];
    #pragma unroll
    for (int o = 0; o < OO; o++) acc[o] = 0.0f;

    const unsigned* st = (const unsigned*)g_state[0];  // final state after 16 steps
    int n0 = c * 512 + sub * 256;
    for (int n = n0; n < n0 + 256; n++) {
        unsigned wrd = __ldg(&st[n * 4 + wsel]);
        float f = (float)((wrd >> bit) & 1u);
        #pragma unroll
        for (int o = 0; o < OO; o++)
            acc[o] += f * __ldg(&wro[o * NN + n]);
    }
    float* p = &g_partial[(size_t)((c * 2 + sub) * 128 + b) * OO];
    #pragma unroll
    for (int o = 0; o < OO; o++) p[o] = acc[o];
}

// ---------------- readout phase 2 ----------------
__global__ void finalize_kernel(const float* __restrict__ b_readout, float* __restrict__ out) {
    int i = blockIdx.x * blockDim.x + threadIdx.x;
    if (i >= BB * OO) return;
    int b = i / OO;
    int o = i % OO;
    float sum = 0.0f;
    for (int c = 0; c < 256; c++)
        sum += g_partial[(size_t)(c * 128 + b) * OO + o];
    sum += b_readout[o];
    out[i] = 1.0f / (1.0f + expf(-sum));
}

// ---------------- launch ----------------
extern "C" void kernel_launch(void* const* d_in, const int* in_sizes, int n_in,
                              void* d_out, int out_size) {
    const int*   x          = (const int*)d_in[0];
    const int*   adj_list   = (const int*)d_in[1];
    const int*   adj_mask   = (const int*)d_in[2];
    const int*   lut        = (const int*)d_in[3];
    const int*   init_state = (const int*)d_in[4];
    const int*   w_in       = (const int*)d_in[5];
    const float* w_readout  = (const float*)d_in[6];
    const float* b_readout  = (const float*)d_in[7];
    float*       out        = (float*)d_out;

    pack_lut_kernel<<<(NN * 32) / 256, 256>>>(lut);
    merge_adj_kernel<<<(NN * 8) / 256, 256>>>(adj_list, adj_mask);
    pack_x_kernel<<<(TT * IBK * 32) / 256, 256>>>(x, w_in);
    init_state_kernel<<<NN / 256, 256>>>(init_state);
    for (int t = 0; t < TT; t++)
        step_kernel<<<NN / 128, 128>>>(t);
    readout_kernel<<<128, 256>>>(w_readout);
    finalize_kernel<<<(BB * OO + 255) / 256, 256>>>(b_readout, out);
}

// round 12
// speedup vs baseline: 1.0032x; 1.0002x over previous
#include <cuda_runtime.h>
#include <cstdint>

// Problem constants
#define NN   65536   // nodes
#define BB   128     // batch
#define TT   16      // timesteps
#define IBK  256     // input bits per step (w_in = arange(IBK))
#define OO   10      // readout outputs

// ---------------- static device scratch ----------------
__device__ uint4    g_state[2][NN + 1];      // batch-packed state; entry NN = permanent zero
__device__ unsigned g_lut[NN * 8];           // 256-bit packed LUT row per node
__device__ int      g_eadj[NN * 8];          // adjacency with mask pre-merged (masked -> NN)
__device__ uint4    g_xp[TT * IBK];          // per-step batch-packed input bits
__device__ float    g_partial[256 * 128 * OO];

// ---------------- preprocessing: pack lut bits (64MB -> 2MB) ----------------
__global__ void pack_lut_kernel(const int* __restrict__ lut) {
    int gw   = (blockIdx.x * blockDim.x + threadIdx.x) >> 5;
    int lane = threadIdx.x & 31;
    const int* row = lut + (size_t)gw * 256;
    unsigned myword = 0;
    #pragma unroll
    for (int w = 0; w < 8; w++) {
        int v = row[w * 32 + lane];
        unsigned bal = __ballot_sync(0xFFFFFFFFu, v & 1);
        if (lane == w) myword = bal;
    }
    if (lane < 8) g_lut[gw * 8 + lane] = myword;
}

// ---------------- preprocessing: merge mask into adjacency ----------------
__global__ void merge_adj_kernel(const int* __restrict__ adj, const int* __restrict__ msk) {
    int i = blockIdx.x * blockDim.x + threadIdx.x;
    int a = adj[i];
    int m = msk[i];
    g_eadj[i] = (m != 0) ? a : NN;
}

// ---------------- preprocessing: pack x into batch-bit words ----------------
__global__ void pack_x_kernel(const int* __restrict__ x, const int* __restrict__ w_in) {
    int gw   = (blockIdx.x * blockDim.x + threadIdx.x) >> 5;
    int lane = threadIdx.x & 31;
    int t = gw >> 8;
    int i = gw & 255;
    unsigned bw[4];
    #pragma unroll
    for (int w = 0; w < 4; w++) {
        int b = w * 32 + lane;
        int v = x[(b * TT + t) * IBK + i];
        bw[w] = __ballot_sync(0xFFFFFFFFu, v & 1);
    }
    if (lane == 0) {
        int node = w_in[i];
        if ((unsigned)node < IBK) {
            uint4 v; v.x = bw[0]; v.y = bw[1]; v.z = bw[2]; v.w = bw[3];
            g_xp[t * IBK + node] = v;
        }
    }
}

// ---------------- init: broadcast init_state across batch, fuse x[t=0] XOR ----------------
__global__ void init_state_kernel(const int* __restrict__ init_state) {
    int n = blockIdx.x * blockDim.x + threadIdx.x;
    unsigned v = (unsigned)(-(init_state[n] & 1));
    uint4 s; s.x = v; s.y = v; s.z = v; s.w = v;
    if (n < IBK) {
        uint4 xv = g_xp[n];     // t = 0
        s.x ^= xv.x; s.y ^= xv.y; s.z ^= xv.z; s.w ^= xv.w;
    }
    g_state[0][n] = s;
    if (n == 0) {
        uint4 z; z.x = z.y = z.z = z.w = 0u;
        g_state[0][NN] = z;
        g_state[1][NN] = z;
    }
}

// ---------------- one reservoir step ----------------
// 128 threads/CTA, 512 CTAs. Conflict-free LDS: LUT stored word-major
// slut[w*128 + tid] -> bank = tid mod 32 regardless of the random word index.
__global__ void __launch_bounds__(128) step_kernel(int t) {
    __shared__ unsigned slut[8 * 128];   // [word][thread] -- bank = tid%32 always
    const int tid = threadIdx.x;
    const int n   = blockIdx.x * 128 + tid;
    const uint4* __restrict__ sin  = g_state[t & 1];
    uint4* __restrict__       sout = g_state[(t + 1) & 1];

    // independent loads first: LUT row + adjacency
    const uint4* lr = (const uint4*)&g_lut[n * 8];
    uint4 lA = __ldg(lr);
    uint4 lB = __ldg(lr + 1);

    const int4* ea4 = (const int4*)g_eadj;
    int4 a0 = __ldg(&ea4[n * 2]);
    int4 a1 = __ldg(&ea4[n * 2 + 1]);

    // issue the 8 random gathers ASAP
    uint4 v0 = __ldg(&sin[a0.x]);
    uint4 v1 = __ldg(&sin[a0.y]);
    uint4 v2 = __ldg(&sin[a0.z]);
    uint4 v3 = __ldg(&sin[a0.w]);
    uint4 v4 = __ldg(&sin[a1.x]);
    uint4 v5 = __ldg(&sin[a1.y]);
    uint4 v6 = __ldg(&sin[a1.z]);
    uint4 v7 = __ldg(&sin[a1.w]);

    // stage LUT row word-major (conflict-free stores: fixed w, lanes distinct banks)
    slut[0 * 128 + tid] = lA.x;
    slut[1 * 128 + tid] = lA.y;
    slut[2 * 128 + tid] = lA.z;
    slut[3 * 128 + tid] = lA.w;
    slut[4 * 128 + tid] = lB.x;
    slut[5 * 128 + tid] = lB.y;
    slut[6 * 128 + tid] = lB.z;
    slut[7 * 128 + tid] = lB.w;
    const unsigned* myl = &slut[tid];   // element w at myl[w*128]

    unsigned nbw[8][4];
    nbw[0][0]=v0.x; nbw[0][1]=v0.y; nbw[0][2]=v0.z; nbw[0][3]=v0.w;
    nbw[1][0]=v1.x; nbw[1][1]=v1.y; nbw[1][2]=v1.z; nbw[1][3]=v1.w;
    nbw[2][0]=v2.x; nbw[2][1]=v2.y; nbw[2][2]=v2.z; nbw[2][3]=v2.w;
    nbw[3][0]=v3.x; nbw[3][1]=v3.y; nbw[3][2]=v3.z; nbw[3][3]=v3.w;
    nbw[4][0]=v4.x; nbw[4][1]=v4.y; nbw[4][2]=v4.z; nbw[4][3]=v4.w;
    nbw[5][0]=v5.x; nbw[5][1]=v5.y; nbw[5][2]=v5.z; nbw[5][3]=v5.w;
    nbw[6][0]=v6.x; nbw[6][1]=v6.y; nbw[6][2]=v6.z; nbw[6][3]=v6.w;
    nbw[7][0]=v7.x; nbw[7][1]=v7.y; nbw[7][2]=v7.z; nbw[7][3]=v7.w;

    unsigned outw[4];
    #pragma unroll
    for (int l = 0; l < 4; l++) {     // 32 batches per lane word
        unsigned r0 = nbw[0][l], r1 = nbw[1][l], r2 = nbw[2][l], r3 = nbw[3][l];
        unsigned r4 = nbw[4][l], r5 = nbw[5][l], r6 = nbw[6][l], r7 = nbw[7][l];
        unsigned acc = 0;
        #pragma unroll
        for (int g = 0; g < 4; g++) { // byte group = 8 batches
            const unsigned s01 = (unsigned)(g | ((g + 4) << 4));
            unsigned t76 = __byte_perm(r7, r6, s01);
            unsigned t54 = __byte_perm(r5, r4, s01);
            unsigned t32 = __byte_perm(r3, r2, s01);
            unsigned t10 = __byte_perm(r1, r0, s01);
            unsigned xl  = __byte_perm(t76, t54, 0x5410);
            unsigned xh  = __byte_perm(t32, t10, 0x5410);

            // fused 8x8 bit transpose of 64-bit (xh:xl)
            unsigned lo = __funnelshift_r(xl, xh, 7);
            unsigned hi = xh >> 7;
            unsigned tl = (xl ^ lo) & 0x00AA00AAu;
            unsigned th = (xh ^ hi) & 0x00AA00AAu;
            xl ^= tl ^ (tl << 7);
            xh ^= th ^ (th << 7);
            lo = __funnelshift_r(xl, xh, 14);
            hi = xh >> 14;
            tl = (xl ^ lo) & 0x0000CCCCu;
            th = (xh ^ hi) & 0x0000CCCCu;
            xl ^= tl ^ (tl << 14);
            xh ^= th ^ (th << 14);
            lo = __funnelshift_r(xl, xh, 28);
            tl = (xl ^ lo) & 0xF0F0F0F0u;
            xl ^= tl;
            xh ^= tl >> 4;

            // byte i of (xh:xl) = 8-bit LUT index of batch 8g+i
            #pragma unroll
            for (int b = 0; b < 8; b++) {
                unsigned src = (b < 4) ? xl : xh;
                unsigned idx = __byte_perm(src, 0u, 0x4440u + (unsigned)(b & 3));
                unsigned w   = myl[(idx >> 5) * 128];
                unsigned pos = (unsigned)(g * 8 + b);
                acc |= __funnelshift_r(w, w, idx - pos) & (1u << pos);
            }
        }
        outw[l] = acc;
    }

    uint4 o; o.x = outw[0]; o.y = outw[1]; o.z = outw[2]; o.w = outw[3];
    if (t < TT - 1 && n < IBK) {
        uint4 xv = g_xp[(t + 1) * IBK + n];
        o.x ^= xv.x; o.y ^= xv.y; o.z ^= xv.z; o.w ^= xv.w;
    }
    sout[n] = o;
}

// ---------------- readout phase 1: deterministic partials ----------------
__global__ void readout_kernel(const float* __restrict__ wro) {
    int c   = blockIdx.x;
    int b   = threadIdx.x & 127;
    int sub = threadIdx.x >> 7;
    int wsel = b >> 5;
    int bit  = b & 31;
    float acc[OO];
    #pragma unroll
    for (int o = 0; o < OO; o++) acc[o] = 0.0f;

    const unsigned* st = (const unsigned*)g_state[0];  // final state after 16 steps
    int n0 = c * 512 + sub * 256;
    for (int n = n0; n < n0 + 256; n++) {
        unsigned wrd = __ldg(&st[n * 4 + wsel]);
        float f = (float)((wrd >> bit) & 1u);
        #pragma unroll
        for (int o = 0; o < OO; o++)
            acc[o] += f * __ldg(&wro[o * NN + n]);
    }
    float* p = &g_partial[(size_t)((c * 2 + sub) * 128 + b) * OO];
    #pragma unroll
    for (int o = 0; o < OO; o++) p[o] = acc[o];
}

// ---------------- readout phase 2 ----------------
__global__ void finalize_kernel(const float* __restrict__ b_readout, float* __restrict__ out) {
    int i = blockIdx.x * blockDim.x + threadIdx.x;
    if (i >= BB * OO) return;
    int b = i / OO;
    int o = i % OO;
    float sum = 0.0f;
    for (int c = 0; c < 256; c++)
        sum += g_partial[(size_t)(c * 128 + b) * OO + o];
    sum += b_readout[o];
    out[i] = 1.0f / (1.0f + expf(-sum));
}

// ---------------- launch ----------------
extern "C" void kernel_launch(void* const* d_in, const int* in_sizes, int n_in,
                              void* d_out, int out_size) {
    const int*   x          = (const int*)d_in[0];
    const int*   adj_list   = (const int*)d_in[1];
    const int*   adj_mask   = (const int*)d_in[2];
    const int*   lut        = (const int*)d_in[3];
    const int*   init_state = (const int*)d_in[4];
    const int*   w_in       = (const int*)d_in[5];
    const float* w_readout  = (const float*)d_in[6];
    const float* b_readout  = (const float*)d_in[7];
    float*       out        = (float*)d_out;

    pack_lut_kernel<<<(NN * 32) / 256, 256>>>(lut);
    merge_adj_kernel<<<(NN * 8) / 256, 256>>>(adj_list, adj_mask);
    pack_x_kernel<<<(TT * IBK * 32) / 256, 256>>>(x, w_in);
    init_state_kernel<<<NN / 256, 256>>>(init_state);
    for (int t = 0; t < TT; t++)
        step_kernel<<<NN / 128, 128>>>(t);
    readout_kernel<<<128, 256>>>(w_readout);
    finalize_kernel<<<(BB * OO + 255) / 256, 256>>>(b_readout, out);
}